// round 14
// baseline (speedup 1.0000x reference)
#include <cuda_runtime.h>
#include <cuda_fp16.h>
#include <cstdint>

// AdaptiveSample (R13 + 4-channel uint2 taps + packed f32x2 FFMA, single phase):
//   weights: softmax over 15 sampled taps of valid*posw*guide (fp32, R13-identical)
//   gather:  all 32 channels staged once as 8 groups of 4 channels packed
//            {half2(c0,c1), half2(c2,c3)} per pixel; per tap: LDS.64 + 2 FFMA2
//   copy:    features passthrough gmem->gmem float4 (bit-exact).

namespace {
constexpr int H  = 256;
constexpr int W  = 512;
constexpr int C  = 32;
constexpr int B  = 2;
constexpr int S  = 15;
constexpr int KS = 5;
constexpr int KK = 25;
constexpr int HW = H * W;

constexpr int BW = 32;
constexpr int BH = 8;
constexpr int NT = BW * BH;

constexpr int FP   = 48;          // halo pitch (px): cols [w0-8, w0+40)
constexpr int FR   = 12;          // halo rows: [h0-2, h0+10)
constexpr int SLOT = FP * FR;     // 576 px per tile
constexpr int NG   = C / 4;       // 8 four-channel groups
constexpr int GUIDEF = BH * BW * KK;  // 6400 guide floats (aliased in raw)
}

__device__ __forceinline__ void ffma2(unsigned long long& acc,
                                      unsigned long long v,
                                      unsigned long long wt) {
    asm("fma.rn.f32x2 %0, %1, %2, %0;" : "+l"(acc) : "l"(v), "l"(wt));
}
__device__ __forceinline__ unsigned long long pack2(float x, float y) {
    unsigned long long r;
    asm("mov.b64 %0, {%1, %2};" : "=l"(r) : "f"(x), "f"(y));
    return r;
}
__device__ __forceinline__ float2 unpack2(unsigned long long v) {
    float2 f;
    asm("mov.b64 {%0, %1}, %2;" : "=f"(f.x), "=f"(f.y) : "l"(v));
    return f;
}

__global__ __launch_bounds__(NT, 5)
void adaptive_sample_kernel(const float* __restrict__ depth,
                            const float* __restrict__ features,
                            const float* __restrict__ guide,
                            const int*   __restrict__ sidx,
                            float* __restrict__ out,
                            float* __restrict__ outf,
                            int do_copy)
{
    __shared__ alignas(16) char raw[NG * SLOT * 8];   // 36864 B: guide tile, then uint2 tiles
    __shared__ float       sh_posw[S];
    __shared__ int         sh_k[S];
    __shared__ signed char sh_dy[S], sh_dx[S];

    float*  shg  = reinterpret_cast<float*>(raw);
    uint2*  qbuf = reinterpret_cast<uint2*>(raw);

    const int tx  = threadIdx.x;
    const int ty  = threadIdx.y;
    const int tid = ty * BW + tx;
    const int w0  = blockIdx.x * BW;
    const int h0  = blockIdx.y * BH;
    const int b   = blockIdx.z;

    // ---- tap metadata (one thread; S=15 trivial) ----
    if (tid == 0) {
        float pw[S];
        float sum = 0.f;
        #pragma unroll
        for (int s = 0; s < S; ++s) {
            int k  = sidx[s];
            int px = k % KS;
            int py = k / KS;
            float fx = (float)px - 2.f;
            float fy = (float)py - 2.f;
            float v  = __expf(-0.5f * sqrtf(fx * fx + fy * fy));
            pw[s] = v; sum += v;
            sh_k[s]  = k;
            sh_dy[s] = (signed char)(py - 2);
            sh_dx[s] = (signed char)(px - 2);
        }
        float inv = 1.f / sum;
        #pragma unroll
        for (int s = 0; s < S; ++s) sh_posw[s] = pw[s] * inv;
    }

    // ---- stage guide tile (contiguous float4 rows; R13-identical) ----
    #pragma unroll
    for (int it = 0; it < (GUIDEF / 4 + NT - 1) / NT; ++it) {
        int i4 = tid + it * NT;
        if (i4 < GUIDEF / 4) {
            int row = i4 / (BW * KK / 4);
            int in4 = i4 - row * (BW * KK / 4);
            const float4* src = reinterpret_cast<const float4*>(
                guide + (((size_t)b * H + (h0 + row)) * W + w0) * KK) + in4;
            reinterpret_cast<float4*>(shg + row * BW * KK)[in4] = *src;
        }
    }
    __syncthreads();

    const int h = h0 + ty;
    const int w = w0 + tx;

    // ---- per-pixel softmax weights + packed smem tap offsets (R13-identical) ----
    const float* drow = depth + (size_t)b * HW;
    const float* gpix = shg + (ty * BW + tx) * KK;   // lane stride 25: conflict-free

    float    wv[S];
    unsigned ptoff[(S + 1) / 2];
    unsigned ibm  = 0u;
    float    gmax = 0.f;  // logits >= 0
    #pragma unroll
    for (int s = 0; s < S; ++s) {
        int dy = (int)sh_dy[s], dx = (int)sh_dx[s];
        int hh = h + dy, ww = w + dx;
        bool ib = ((unsigned)hh < (unsigned)H) && ((unsigned)ww < (unsigned)W);
        float d = ib ? __ldg(drow + hh * W + ww) : 0.f;
        bool valid = ib && (d > 0.f) && (d < 192.0f);
        float logit = valid ? sh_posw[s] * gpix[sh_k[s]] : 0.f;
        wv[s] = logit;
        gmax  = fmaxf(gmax, logit);
        ibm  |= (unsigned)ib << s;
        int o = (ty + 2 + dy) * FP + (tx + 8 + dx);
        if ((s & 1) == 0) ptoff[s >> 1]  = (unsigned)o;
        else              ptoff[s >> 1] |= (unsigned)o << 16;
    }
    float esum = 0.f;
    #pragma unroll
    for (int s = 0; s < S; ++s) { wv[s] = __expf(wv[s] - gmax); esum += wv[s]; }
    float inv = 1.f / esum;
    #pragma unroll
    for (int s = 0; s < S; ++s)
        wv[s] = ((ibm >> s) & 1u) ? wv[s] * inv : 0.f;  // OOB tap == zero-padded feature

    __syncthreads();  // guide reads done; raw becomes packed feature buffer

    const float* fbase = features + (size_t)b * C * HW;
    float*       obase = out + (size_t)b * C * HW + (size_t)h * W + w;

    // ---- stage all 32 channels: unit = 4 channels x 4 px -> 4 LDG.128 + 2 STS.128 ----
    #pragma unroll
    for (int it = 0; it < 5; ++it) {                  // 1152 units / 256 thr
        int i = tid + it * NT;
        if (i < NG * FR * (FP / 4)) {
            int g   = i / (FR * FP / 4);              // /144
            int rem = i - g * (FR * FP / 4);
            int r   = rem / (FP / 4);                 // /12
            int q   = rem - r * (FP / 4);
            int gh  = min(max(h0 + r - 2, 0), H - 1);
            int gc  = min(max(w0 - 8 + q * 4, 0), W - 4);
            const float* src = fbase + (size_t)(g * 4) * HW + gh * W + gc;
            float4 v0 = __ldg(reinterpret_cast<const float4*>(src));
            float4 v1 = __ldg(reinterpret_cast<const float4*>(src + HW));
            float4 v2 = __ldg(reinterpret_cast<const float4*>(src + 2 * HW));
            float4 v3 = __ldg(reinterpret_cast<const float4*>(src + 3 * HW));
            __half2 p01x = __floats2half2_rn(v0.x, v1.x), p23x = __floats2half2_rn(v2.x, v3.x);
            __half2 p01y = __floats2half2_rn(v0.y, v1.y), p23y = __floats2half2_rn(v2.y, v3.y);
            __half2 p01z = __floats2half2_rn(v0.z, v1.z), p23z = __floats2half2_rn(v2.z, v3.z);
            __half2 p01w = __floats2half2_rn(v0.w, v1.w), p23w = __floats2half2_rn(v2.w, v3.w);
            uint4 lo, hi;
            lo.x = *reinterpret_cast<uint32_t*>(&p01x);
            lo.y = *reinterpret_cast<uint32_t*>(&p23x);
            lo.z = *reinterpret_cast<uint32_t*>(&p01y);
            lo.w = *reinterpret_cast<uint32_t*>(&p23y);
            hi.x = *reinterpret_cast<uint32_t*>(&p01z);
            hi.y = *reinterpret_cast<uint32_t*>(&p23z);
            hi.z = *reinterpret_cast<uint32_t*>(&p01w);
            hi.w = *reinterpret_cast<uint32_t*>(&p23w);
            uint4* dst = reinterpret_cast<uint4*>(qbuf + g * SLOT + r * FP + q * 4);
            dst[0] = lo;   // pixels q*4, q*4+1
            dst[1] = hi;   // pixels q*4+2, q*4+3
        }
    }
    __syncthreads();

    // ---- hot loop: per 4-channel group, 15 x (LDS.64 + 2 FFMA2) ----
    #pragma unroll 1
    for (int g = 0; g < NG; ++g) {
        const uint2* bg = qbuf + g * SLOT;
        unsigned long long a01 = 0ull, a23 = 0ull;
        #pragma unroll
        for (int s = 0; s < S; ++s) {
            int o = (int)((ptoff[s >> 1] >> ((s & 1) * 16)) & 0xffffu);
            uint2 v = bg[o];
            float2 f01 = __half22float2(*reinterpret_cast<__half2*>(&v.x));
            float2 f23 = __half22float2(*reinterpret_cast<__half2*>(&v.y));
            unsigned long long wt2 = pack2(wv[s], wv[s]);
            ffma2(a01, pack2(f01.x, f01.y), wt2);
            ffma2(a23, pack2(f23.x, f23.y), wt2);
        }
        float2 r01 = unpack2(a01);
        float2 r23 = unpack2(a23);
        obase[(size_t)(g * 4 + 0) * HW] = r01.x;
        obase[(size_t)(g * 4 + 1) * HW] = r01.y;
        obase[(size_t)(g * 4 + 2) * HW] = r23.x;
        obase[(size_t)(g * 4 + 3) * HW] = r23.y;
    }

    // ---- passthrough copy, gmem->gmem float4 (bit-exact; tile is L2-hot) ----
    if (do_copy) {
        float* ocbase = outf + (size_t)b * C * HW;
        #pragma unroll
        for (int it = 0; it < (C * BH * BW / 4) / NT; ++it) {   // 8
            int i   = tid + it * NT;
            int c   = i >> 6;
            int rem = i & 63;
            int r   = rem >> 3;
            int q4  = rem & 7;
            size_t off = (size_t)c * HW + (size_t)(h0 + r) * W + w0 + q4 * 4;
            float4 v = __ldg(reinterpret_cast<const float4*>(fbase + off));
            *reinterpret_cast<float4*>(ocbase + off) = v;
        }
    }
}

extern "C" void kernel_launch(void* const* d_in, const int* in_sizes, int n_in,
                              void* d_out, int out_size)
{
    const float* depth    = (const float*)d_in[0];
    const float* features = (const float*)d_in[1];
    const float* guide    = (const float*)d_in[2];
    const int*   sidx     = (const int*)d_in[3];

    float* out = (float*)d_out;
    const int featN = in_sizes[1];                       // B*C*H*W
    const int do_copy = (out_size >= 2 * featN) ? 1 : 0; // tuple output: (out, features)
    float* outf = out + featN;

    dim3 block(BW, BH);
    dim3 grid(W / BW, H / BH, B);
    adaptive_sample_kernel<<<grid, block>>>(depth, features, guide, sidx,
                                            out, outf, do_copy);
}

// round 15
// speedup vs baseline: 1.0310x; 1.0310x over previous
#include <cuda_runtime.h>
#include <cuda_fp16.h>
#include <cstdint>

// AdaptiveSample (R13 + register diet -> 6 blocks/SM):
//   weights: softmax over 15 sampled taps of valid*posw*guide (fp32 math),
//            then compressed to 8 half2 registers
//   gather:  2 phases x 16 channels; tiles stored as half2 (ch c, ch c+1) pairs;
//            one LDS.32 per tap serves 2 channels
//   copy:    features passthrough gmem->gmem float4 (bit-exact).

namespace {
constexpr int H  = 256;
constexpr int W  = 512;
constexpr int C  = 32;
constexpr int B  = 2;
constexpr int S  = 15;
constexpr int KS = 5;
constexpr int KK = 25;
constexpr int HW = H * W;

constexpr int BW = 32;            // tile width (warp-coalesced)
constexpr int BH = 8;             // tile height
constexpr int NT = BW * BH;       // 256 threads

constexpr int FP    = 48;         // halo pitch (px): cols [w0-8, w0+40)
constexpr int FR    = 12;         // halo rows: [h0-2, h0+10)
constexpr int SLOT  = FP * FR;    // 576 px per tile
constexpr int PC    = 16;         // channels per phase
constexpr int NP    = C / PC;     // 2 phases
constexpr int NPAIR = PC / 2;     // 8 half2 channel-pairs per phase
constexpr int GBUF  = BH * BW * KK;  // guide tile floats (6400); feature half2 buf
                                     // needs 8*576 uints = 4608 <= 6400 (aliased)
}

__global__ __launch_bounds__(NT, 6)
void adaptive_sample_kernel(const float* __restrict__ depth,
                            const float* __restrict__ features,
                            const float* __restrict__ guide,
                            const int*   __restrict__ sidx,
                            float* __restrict__ out,
                            float* __restrict__ outf,
                            int do_copy)
{
    __shared__ float       shbuf[GBUF];   // guide tile, then (aliased) half2 feature tiles
    __shared__ float       sh_posw[S];
    __shared__ int         sh_k[S];
    __shared__ signed char sh_dy[S], sh_dx[S];

    const int tx  = threadIdx.x;
    const int ty  = threadIdx.y;
    const int tid = ty * BW + tx;
    const int w0  = blockIdx.x * BW;
    const int h0  = blockIdx.y * BH;
    const int b   = blockIdx.z;

    // ---- tap metadata (one thread; S=15 trivial) ----
    if (tid == 0) {
        float pw[S];
        float sum = 0.f;
        #pragma unroll
        for (int s = 0; s < S; ++s) {
            int k  = sidx[s];
            int px = k % KS;
            int py = k / KS;
            float fx = (float)px - 2.f;
            float fy = (float)py - 2.f;
            float v  = __expf(-0.5f * sqrtf(fx * fx + fy * fy));
            pw[s] = v; sum += v;
            sh_k[s]  = k;
            sh_dy[s] = (signed char)(py - 2);
            sh_dx[s] = (signed char)(px - 2);
        }
        float inv = 1.f / sum;
        #pragma unroll
        for (int s = 0; s < S; ++s) sh_posw[s] = pw[s] * inv;
    }

    // ---- stage guide tile (contiguous float4 rows; R13-identical) ----
    #pragma unroll
    for (int it = 0; it < (GBUF / 4 + NT - 1) / NT; ++it) {
        int i4 = tid + it * NT;
        if (i4 < GBUF / 4) {
            int row = i4 / (BW * KK / 4);
            int in4 = i4 - row * (BW * KK / 4);
            const float4* src = reinterpret_cast<const float4*>(
                guide + (((size_t)b * H + (h0 + row)) * W + w0) * KK) + in4;
            reinterpret_cast<float4*>(shbuf + row * BW * KK)[in4] = *src;
        }
    }
    __syncthreads();

    const int h = h0 + ty;
    const int w = w0 + tx;

    // ---- per-pixel softmax weights (fp32) + packed offsets; weights -> 8 half2 regs ----
    const float* drow = depth + (size_t)b * HW;
    const float* gpix = shbuf + (ty * BW + tx) * KK;   // lane stride 25: conflict-free

    __half2  hwv[(S + 1) / 2];         // 8 regs: weight pairs (s, s+1)
    unsigned ptoff[(S + 1) / 2];       // 8 regs: packed 16-bit pixel offsets
    {
        float    wv[S];
        unsigned ibm  = 0u;
        float    gmax = 0.f;  // logits >= 0
        #pragma unroll
        for (int s = 0; s < S; ++s) {
            int dy = (int)sh_dy[s], dx = (int)sh_dx[s];
            int hh = h + dy, ww = w + dx;
            bool ib = ((unsigned)hh < (unsigned)H) && ((unsigned)ww < (unsigned)W);
            float d = ib ? __ldg(drow + hh * W + ww) : 0.f;
            bool valid = ib && (d > 0.f) && (d < 192.0f);
            float logit = valid ? sh_posw[s] * gpix[sh_k[s]] : 0.f;
            wv[s] = logit;
            gmax  = fmaxf(gmax, logit);
            ibm  |= (unsigned)ib << s;
            int o = (ty + 2 + dy) * FP + (tx + 8 + dx);
            if ((s & 1) == 0) ptoff[s >> 1]  = (unsigned)o;
            else              ptoff[s >> 1] |= (unsigned)o << 16;
        }
        float esum = 0.f;
        #pragma unroll
        for (int s = 0; s < S; ++s) { wv[s] = __expf(wv[s] - gmax); esum += wv[s]; }
        float inv = 1.f / esum;
        #pragma unroll
        for (int s = 0; s < S; ++s)
            wv[s] = ((ibm >> s) & 1u) ? wv[s] * inv : 0.f;  // OOB tap == zero-pad
        #pragma unroll
        for (int i = 0; i < (S + 1) / 2; ++i)
            hwv[i] = __floats2half2_rn(wv[2 * i], (2 * i + 1 < S) ? wv[2 * i + 1] : 0.f);
    }

    __syncthreads();  // guide reads done; shbuf becomes half2 feature buffer

    uint32_t* hbuf = reinterpret_cast<uint32_t*>(shbuf);   // half2 per entry

    const float* fbase = features + (size_t)b * C * HW;
    float*       obase = out + (size_t)b * C * HW + (size_t)h * W + w;

    #pragma unroll
    for (int ph = 0; ph < NP; ++ph) {
        const int c0 = ph * PC;

        // ---- stage 8 channel-pairs as half2 tiles (R13-identical) ----
        #pragma unroll
        for (int it = 0; it < 5; ++it) {                    // 1152 units / 256 thr
            int i = tid + it * NT;
            if (i < NPAIR * FR * (FP / 4)) {
                int pair = i / (FR * FP / 4);               // /144
                int rem  = i - pair * (FR * FP / 4);
                int r    = rem / (FP / 4);                  // /12
                int q    = rem - r * (FP / 4);
                int gh   = min(max(h0 + r - 2, 0), H - 1);
                int gc   = min(max(w0 - 8 + q * 4, 0), W - 4);
                const float* src = fbase + (size_t)(c0 + pair * 2) * HW + gh * W + gc;
                float4 vA = __ldg(reinterpret_cast<const float4*>(src));
                float4 vB = __ldg(reinterpret_cast<const float4*>(src + HW));
                __half2 h0p = __floats2half2_rn(vA.x, vB.x);
                __half2 h1p = __floats2half2_rn(vA.y, vB.y);
                __half2 h2p = __floats2half2_rn(vA.z, vB.z);
                __half2 h3p = __floats2half2_rn(vA.w, vB.w);
                uint4 u;
                u.x = *reinterpret_cast<uint32_t*>(&h0p);
                u.y = *reinterpret_cast<uint32_t*>(&h1p);
                u.z = *reinterpret_cast<uint32_t*>(&h2p);
                u.w = *reinterpret_cast<uint32_t*>(&h3p);
                *reinterpret_cast<uint4*>(hbuf + pair * SLOT + r * FP + q * 4) = u;
            }
        }
        __syncthreads();

        // ---- compute: 2 chunks of 4 pairs; per tap one LDS.32 serves 2 channels ----
        #pragma unroll
        for (int pg = 0; pg < NPAIR; pg += 4) {
            float2 a0 = {0.f, 0.f}, a1 = {0.f, 0.f}, a2 = {0.f, 0.f}, a3 = {0.f, 0.f};
            const uint32_t* b0 = hbuf + (pg + 0) * SLOT;
            const uint32_t* b1 = hbuf + (pg + 1) * SLOT;
            const uint32_t* b2 = hbuf + (pg + 2) * SLOT;
            const uint32_t* b3 = hbuf + (pg + 3) * SLOT;
            #pragma unroll
            for (int s = 0; s < S; ++s) {
                int   o  = (int)((ptoff[s >> 1] >> ((s & 1) * 16)) & 0xffffu);
                float wt = __half2float((s & 1) ? __high2half(hwv[s >> 1])
                                                : __low2half(hwv[s >> 1]));
                uint32_t u0 = b0[o], u1 = b1[o], u2 = b2[o], u3 = b3[o];
                float2 f0 = __half22float2(*reinterpret_cast<__half2*>(&u0));
                float2 f1 = __half22float2(*reinterpret_cast<__half2*>(&u1));
                float2 f2 = __half22float2(*reinterpret_cast<__half2*>(&u2));
                float2 f3 = __half22float2(*reinterpret_cast<__half2*>(&u3));
                a0.x = fmaf(wt, f0.x, a0.x); a0.y = fmaf(wt, f0.y, a0.y);
                a1.x = fmaf(wt, f1.x, a1.x); a1.y = fmaf(wt, f1.y, a1.y);
                a2.x = fmaf(wt, f2.x, a2.x); a2.y = fmaf(wt, f2.y, a2.y);
                a3.x = fmaf(wt, f3.x, a3.x); a3.y = fmaf(wt, f3.y, a3.y);
            }
            obase[(size_t)(c0 + 2 * (pg + 0)) * HW]     = a0.x;
            obase[(size_t)(c0 + 2 * (pg + 0) + 1) * HW] = a0.y;
            obase[(size_t)(c0 + 2 * (pg + 1)) * HW]     = a1.x;
            obase[(size_t)(c0 + 2 * (pg + 1) + 1) * HW] = a1.y;
            obase[(size_t)(c0 + 2 * (pg + 2)) * HW]     = a2.x;
            obase[(size_t)(c0 + 2 * (pg + 2) + 1) * HW] = a2.y;
            obase[(size_t)(c0 + 2 * (pg + 3)) * HW]     = a3.x;
            obase[(size_t)(c0 + 2 * (pg + 3) + 1) * HW] = a3.y;
        }
        __syncthreads();
    }

    // ---- passthrough copy, gmem->gmem float4 (bit-exact; tile is L2-hot) ----
    if (do_copy) {
        float* ocbase = outf + (size_t)b * C * HW;
        #pragma unroll
        for (int it = 0; it < (C * BH * BW / 4) / NT; ++it) {   // 8
            int i   = tid + it * NT;
            int c   = i >> 6;
            int rem = i & 63;
            int r   = rem >> 3;
            int q4  = rem & 7;
            size_t off = (size_t)c * HW + (size_t)(h0 + r) * W + w0 + q4 * 4;
            float4 v = __ldg(reinterpret_cast<const float4*>(fbase + off));
            *reinterpret_cast<float4*>(ocbase + off) = v;
        }
    }
}

extern "C" void kernel_launch(void* const* d_in, const int* in_sizes, int n_in,
                              void* d_out, int out_size)
{
    const float* depth    = (const float*)d_in[0];
    const float* features = (const float*)d_in[1];
    const float* guide    = (const float*)d_in[2];
    const int*   sidx     = (const int*)d_in[3];

    float* out = (float*)d_out;
    const int featN = in_sizes[1];                       // B*C*H*W
    const int do_copy = (out_size >= 2 * featN) ? 1 : 0; // tuple output: (out, features)
    float* outf = out + featN;

    dim3 block(BW, BH);
    dim3 grid(W / BW, H / BH, B);
    adaptive_sample_kernel<<<grid, block>>>(depth, features, guide, sidx,
                                            out, outf, do_copy);
}

// round 16
// speedup vs baseline: 1.1230x; 1.0893x over previous
#include <cuda_runtime.h>
#include <cuda_fp16.h>
#include <cstdint>

// AdaptiveSample (R13 skeleton + HFMA2 hot loop + precomputed smem addresses):
//   weights: softmax over 15 sampled taps of valid*posw*guide (fp32, R13-identical)
//   gather:  2 phases x 16 channels; tiles stored as half2 (ch c, ch c+1) pairs;
//            per tap-chunk: 4 LDS.32 + 4 HFMA2; fp32 flush every 8 taps
//   copy:    features passthrough gmem->gmem float4 (bit-exact).

namespace {
constexpr int H  = 256;
constexpr int W  = 512;
constexpr int C  = 32;
constexpr int B  = 2;
constexpr int S  = 15;
constexpr int KS = 5;
constexpr int KK = 25;
constexpr int HW = H * W;

constexpr int BW = 32;            // tile width (warp-coalesced)
constexpr int BH = 8;             // tile height
constexpr int NT = BW * BH;       // 256 threads

constexpr int FP    = 48;         // halo pitch (px): cols [w0-8, w0+40)
constexpr int FR    = 12;         // halo rows: [h0-2, h0+10)
constexpr int SLOT  = FP * FR;    // 576 px per tile
constexpr int PC    = 16;         // channels per phase
constexpr int NP    = C / PC;     // 2 phases
constexpr int NPAIR = PC / 2;     // 8 half2 channel-pairs per phase
constexpr int GBUF  = BH * BW * KK;  // guide tile floats (6400); half2 buf (4608) aliases
}

__device__ __forceinline__ uint32_t lds_u32(uint32_t addr) {
    uint32_t v;
    asm volatile("ld.shared.b32 %0, [%1];" : "=r"(v) : "r"(addr));
    return v;
}

__global__ __launch_bounds__(NT, 5)
void adaptive_sample_kernel(const float* __restrict__ depth,
                            const float* __restrict__ features,
                            const float* __restrict__ guide,
                            const int*   __restrict__ sidx,
                            float* __restrict__ out,
                            float* __restrict__ outf,
                            int do_copy)
{
    __shared__ float       shbuf[GBUF];   // guide tile, then (aliased) half2 feature tiles
    __shared__ float       sh_posw[S];
    __shared__ int         sh_k[S];
    __shared__ signed char sh_dy[S], sh_dx[S];

    const int tx  = threadIdx.x;
    const int ty  = threadIdx.y;
    const int tid = ty * BW + tx;
    const int w0  = blockIdx.x * BW;
    const int h0  = blockIdx.y * BH;
    const int b   = blockIdx.z;

    const uint32_t sbase = (uint32_t)__cvta_generic_to_shared(shbuf);

    // ---- tap metadata (one thread; S=15 trivial) ----
    if (tid == 0) {
        float pw[S];
        float sum = 0.f;
        #pragma unroll
        for (int s = 0; s < S; ++s) {
            int k  = sidx[s];
            int px = k % KS;
            int py = k / KS;
            float fx = (float)px - 2.f;
            float fy = (float)py - 2.f;
            float v  = __expf(-0.5f * sqrtf(fx * fx + fy * fy));
            pw[s] = v; sum += v;
            sh_k[s]  = k;
            sh_dy[s] = (signed char)(py - 2);
            sh_dx[s] = (signed char)(px - 2);
        }
        float inv = 1.f / sum;
        #pragma unroll
        for (int s = 0; s < S; ++s) sh_posw[s] = pw[s] * inv;
    }

    // ---- stage guide tile (contiguous float4 rows; R13-identical) ----
    #pragma unroll
    for (int it = 0; it < (GBUF / 4 + NT - 1) / NT; ++it) {
        int i4 = tid + it * NT;
        if (i4 < GBUF / 4) {
            int row = i4 / (BW * KK / 4);
            int in4 = i4 - row * (BW * KK / 4);
            const float4* src = reinterpret_cast<const float4*>(
                guide + (((size_t)b * H + (h0 + row)) * W + w0) * KK) + in4;
            reinterpret_cast<float4*>(shbuf + row * BW * KK)[in4] = *src;
        }
    }
    __syncthreads();

    const int h = h0 + ty;
    const int w = w0 + tx;

    // ---- per-pixel softmax weights (fp32) -> half2 broadcast regs + byte addrs ----
    const float* drow = depth + (size_t)b * HW;
    const float* gpix = shbuf + (ty * BW + tx) * KK;   // lane stride 25: conflict-free

    __half2  hwv[S];       // (w_s, w_s)
    uint32_t abyte[S];     // smem byte address of tap pixel in pair-buffer 0
    {
        float    wv[S];
        unsigned ibm  = 0u;
        float    gmax = 0.f;  // logits >= 0
        #pragma unroll
        for (int s = 0; s < S; ++s) {
            int dy = (int)sh_dy[s], dx = (int)sh_dx[s];
            int hh = h + dy, ww = w + dx;
            bool ib = ((unsigned)hh < (unsigned)H) && ((unsigned)ww < (unsigned)W);
            float d = ib ? __ldg(drow + hh * W + ww) : 0.f;
            bool valid = ib && (d > 0.f) && (d < 192.0f);
            float logit = valid ? sh_posw[s] * gpix[sh_k[s]] : 0.f;
            wv[s] = logit;
            gmax  = fmaxf(gmax, logit);
            ibm  |= (unsigned)ib << s;
            abyte[s] = sbase + (uint32_t)((ty + 2 + dy) * FP + (tx + 8 + dx)) * 4u;
        }
        float esum = 0.f;
        #pragma unroll
        for (int s = 0; s < S; ++s) { wv[s] = __expf(wv[s] - gmax); esum += wv[s]; }
        float inv = 1.f / esum;
        #pragma unroll
        for (int s = 0; s < S; ++s) {
            float ws = ((ibm >> s) & 1u) ? wv[s] * inv : 0.f;  // OOB tap == zero-pad
            hwv[s] = __half2half2(__float2half_rn(ws));
        }
    }

    __syncthreads();  // guide reads done; shbuf becomes half2 feature buffer

    uint32_t* hbuf = reinterpret_cast<uint32_t*>(shbuf);   // half2 per entry

    const float* fbase = features + (size_t)b * C * HW;
    float*       obase = out + (size_t)b * C * HW + (size_t)h * W + w;

    #pragma unroll
    for (int ph = 0; ph < NP; ++ph) {
        const int c0 = ph * PC;

        // ---- stage 8 channel-pairs as half2 tiles (R13-identical) ----
        #pragma unroll
        for (int it = 0; it < 5; ++it) {                    // 1152 units / 256 thr
            int i = tid + it * NT;
            if (i < NPAIR * FR * (FP / 4)) {
                int pair = i / (FR * FP / 4);               // /144
                int rem  = i - pair * (FR * FP / 4);
                int r    = rem / (FP / 4);                  // /12
                int q    = rem - r * (FP / 4);
                int gh   = min(max(h0 + r - 2, 0), H - 1);
                int gc   = min(max(w0 - 8 + q * 4, 0), W - 4);
                const float* src = fbase + (size_t)(c0 + pair * 2) * HW + gh * W + gc;
                float4 vA = __ldg(reinterpret_cast<const float4*>(src));
                float4 vB = __ldg(reinterpret_cast<const float4*>(src + HW));
                __half2 h0p = __floats2half2_rn(vA.x, vB.x);
                __half2 h1p = __floats2half2_rn(vA.y, vB.y);
                __half2 h2p = __floats2half2_rn(vA.z, vB.z);
                __half2 h3p = __floats2half2_rn(vA.w, vB.w);
                uint4 u;
                u.x = *reinterpret_cast<uint32_t*>(&h0p);
                u.y = *reinterpret_cast<uint32_t*>(&h1p);
                u.z = *reinterpret_cast<uint32_t*>(&h2p);
                u.w = *reinterpret_cast<uint32_t*>(&h3p);
                *reinterpret_cast<uint4*>(hbuf + pair * SLOT + r * FP + q * 4) = u;
            }
        }
        __syncthreads();

        // ---- hot loop: 2 chunks of 4 pairs; per tap 4 LDS.32 + 4 HFMA2;
        //      fp32 flush after taps 0-7 and 8-14 ----
        #pragma unroll
        for (int pg = 0; pg < NPAIR; pg += 4) {
            const uint32_t pgoff = (uint32_t)(pg * SLOT * 4);
            float2  f0 = {0.f, 0.f}, f1 = {0.f, 0.f}, f2 = {0.f, 0.f}, f3 = {0.f, 0.f};
            __half2 a0 = __half2half2(__ushort_as_half(0)),
                    a1 = a0, a2 = a0, a3 = a0;
            #pragma unroll
            for (int s = 0; s < S; ++s) {
                uint32_t base = abyte[s] + pgoff;
                uint32_t u0 = lds_u32(base);
                uint32_t u1 = lds_u32(base + 1 * SLOT * 4);
                uint32_t u2 = lds_u32(base + 2 * SLOT * 4);
                uint32_t u3 = lds_u32(base + 3 * SLOT * 4);
                __half2 wt = hwv[s];
                a0 = __hfma2(*reinterpret_cast<__half2*>(&u0), wt, a0);
                a1 = __hfma2(*reinterpret_cast<__half2*>(&u1), wt, a1);
                a2 = __hfma2(*reinterpret_cast<__half2*>(&u2), wt, a2);
                a3 = __hfma2(*reinterpret_cast<__half2*>(&u3), wt, a3);
                if (s == 7) {   // mid flush keeps half partials small
                    float2 t;
                    t = __half22float2(a0); f0.x += t.x; f0.y += t.y;
                    t = __half22float2(a1); f1.x += t.x; f1.y += t.y;
                    t = __half22float2(a2); f2.x += t.x; f2.y += t.y;
                    t = __half22float2(a3); f3.x += t.x; f3.y += t.y;
                    a0 = a1 = a2 = a3 = __half2half2(__ushort_as_half(0));
                }
            }
            float2 t;
            t = __half22float2(a0); f0.x += t.x; f0.y += t.y;
            t = __half22float2(a1); f1.x += t.x; f1.y += t.y;
            t = __half22float2(a2); f2.x += t.x; f2.y += t.y;
            t = __half22float2(a3); f3.x += t.x; f3.y += t.y;

            obase[(size_t)(c0 + 2 * (pg + 0)) * HW]     = f0.x;
            obase[(size_t)(c0 + 2 * (pg + 0) + 1) * HW] = f0.y;
            obase[(size_t)(c0 + 2 * (pg + 1)) * HW]     = f1.x;
            obase[(size_t)(c0 + 2 * (pg + 1) + 1) * HW] = f1.y;
            obase[(size_t)(c0 + 2 * (pg + 2)) * HW]     = f2.x;
            obase[(size_t)(c0 + 2 * (pg + 2) + 1) * HW] = f2.y;
            obase[(size_t)(c0 + 2 * (pg + 3)) * HW]     = f3.x;
            obase[(size_t)(c0 + 2 * (pg + 3) + 1) * HW] = f3.y;
        }
        __syncthreads();
    }

    // ---- passthrough copy, gmem->gmem float4 (bit-exact; tile is L2-hot) ----
    if (do_copy) {
        float* ocbase = outf + (size_t)b * C * HW;
        #pragma unroll
        for (int it = 0; it < (C * BH * BW / 4) / NT; ++it) {   // 8
            int i   = tid + it * NT;
            int c   = i >> 6;
            int rem = i & 63;
            int r   = rem >> 3;
            int q4  = rem & 7;
            size_t off = (size_t)c * HW + (size_t)(h0 + r) * W + w0 + q4 * 4;
            float4 v = __ldg(reinterpret_cast<const float4*>(fbase + off));
            *reinterpret_cast<float4*>(ocbase + off) = v;
        }
    }
}

extern "C" void kernel_launch(void* const* d_in, const int* in_sizes, int n_in,
                              void* d_out, int out_size)
{
    const float* depth    = (const float*)d_in[0];
    const float* features = (const float*)d_in[1];
    const float* guide    = (const float*)d_in[2];
    const int*   sidx     = (const int*)d_in[3];

    float* out = (float*)d_out;
    const int featN = in_sizes[1];                       // B*C*H*W
    const int do_copy = (out_size >= 2 * featN) ? 1 : 0; // tuple output: (out, features)
    float* outf = out + featN;

    dim3 block(BW, BH);
    dim3 grid(W / BW, H / BH, B);
    adaptive_sample_kernel<<<grid, block>>>(depth, features, guide, sidx,
                                            out, outf, do_copy);
}